// round 6
// baseline (speedup 1.0000x reference)
#include <cuda_runtime.h>
#include <cuda_bf16.h>
#include <cstdint>

#define H 256
#define MAXROWS 50000
#define PADROWS 50048            // 782 * 64
#define LN_EPS 1e-5f

// ---------------------------------------------------------------------------
// Scratch (__device__ globals: allocation-free rule)
// ---------------------------------------------------------------------------
__device__ float g_agg[MAXROWS * H];
// intermediate h as bf16 hi/lo planes, packed as bf16x2 in uint32 (128 per row)
__device__ uint32_t g_hhi[PADROWS * (H / 2)];
__device__ uint32_t g_hlo[PADROWS * (H / 2)];
// Transposed weights as bf16 hi/lo: [which 0..3][hi/lo][n*H + k]
__device__ __nv_bfloat16 g_wt[4][2][H * H];

// ---------------------------------------------------------------------------
// PTX helpers
// ---------------------------------------------------------------------------
__device__ __forceinline__ uint32_t smem_u32(const void* p) {
    uint32_t a;
    asm("{ .reg .u64 t; cvta.to.shared.u64 t, %1; cvt.u32.u64 %0, t; }"
        : "=r"(a) : "l"(p));
    return a;
}
__device__ __forceinline__ void ldsm_x4(uint32_t r[4], uint32_t addr) {
    asm volatile("ldmatrix.sync.aligned.m8n8.x4.shared.b16 {%0,%1,%2,%3}, [%4];"
                 : "=r"(r[0]), "=r"(r[1]), "=r"(r[2]), "=r"(r[3]) : "r"(addr));
}
__device__ __forceinline__ void mma_bf16(float c[4],
                                         const uint32_t a[4],
                                         uint32_t b0, uint32_t b1) {
    asm volatile(
        "mma.sync.aligned.m16n8k16.row.col.f32.bf16.bf16.f32 "
        "{%0,%1,%2,%3}, {%4,%5,%6,%7}, {%8,%9}, {%0,%1,%2,%3};"
        : "+f"(c[0]), "+f"(c[1]), "+f"(c[2]), "+f"(c[3])
        : "r"(a[0]), "r"(a[1]), "r"(a[2]), "r"(a[3]), "r"(b0), "r"(b1));
}
__device__ __forceinline__ void cp16(uint32_t dst, const void* src) {
    asm volatile("cp.async.ca.shared.global [%0], [%1], 16;"
                 :: "r"(dst), "l"(src) : "memory");
}
#define CP_COMMIT() asm volatile("cp.async.commit_group;" ::: "memory")
#define CP_WAIT1()  asm volatile("cp.async.wait_group 1;" ::: "memory")
#define CP_WAIT0()  asm volatile("cp.async.wait_group 0;" ::: "memory")

__device__ __forceinline__ void red_v4(float* addr, float a, float b,
                                       float c, float d) {
    asm volatile("red.global.add.v4.f32 [%0], {%1,%2,%3,%4};"
                 :: "l"(addr), "f"(a), "f"(b), "f"(c), "f"(d) : "memory");
}
__device__ __forceinline__ uint32_t pack2(float a, float b) {
    __nv_bfloat162 h = __floats2bfloat162_rn(a, b);
    return *(uint32_t*)&h;
}

// ---------------------------------------------------------------------------
// SMEM layout (bytes). A: [64][40] bf16 rows (80B stride). W: [256][40] bf16.
// ---------------------------------------------------------------------------
#define SA_H(st)  ((st) * 5120)
#define SA_LD     10240
#define SW_H(st)  (20480 + (st) * 20480)
#define SW_LD     40960
#define S_BIAS    102400
#define S_G       103424
#define S_BETA    104448
#define S_PSUM    105472
#define S_PSQ     105984
#define SMEM_SZ   106496

// ---------------------------------------------------------------------------
// zero-fill
// ---------------------------------------------------------------------------
__global__ void zero_kernel(float4* __restrict__ p, int n4) {
    int i = blockIdx.x * blockDim.x + threadIdx.x;
    if (i < n4) p[i] = make_float4(0.f, 0.f, 0.f, 0.f);
}

// ---------------------------------------------------------------------------
// Weight prep (all 4 weights in one launch, coalesced smem transpose)
// ---------------------------------------------------------------------------
__global__ void wprep4_kernel(const float* __restrict__ W0,
                              const float* __restrict__ W1,
                              const float* __restrict__ W2,
                              const float* __restrict__ W3,
                              __nv_bfloat16* __restrict__ base) {
    __shared__ float tile[32][33];
    const int which = blockIdx.x >> 6;
    const float* W = (which == 0) ? W0 : (which == 1) ? W1
                   : (which == 2) ? W2 : W3;
    __nv_bfloat16* hi = base + (size_t)which * 2 * H * H;
    __nv_bfloat16* lo = hi + H * H;
    const int b  = blockIdx.x & 63;
    const int tx = threadIdx.x & 31;
    const int ty = threadIdx.x >> 5;
    const int bx = b & 7;
    const int by = b >> 3;
#pragma unroll
    for (int i = 0; i < 4; i++)
        tile[ty + i * 8][tx] = W[(by * 32 + ty + i * 8) * H + bx * 32 + tx];
    __syncthreads();
#pragma unroll
    for (int i = 0; i < 4; i++) {
        float v = tile[tx][ty + i * 8];
        __nv_bfloat16 h = __float2bfloat16(v);
        int n = bx * 32 + ty + i * 8;
        int k = by * 32 + tx;
        hi[n * H + k] = h;
        lo[n * H + k] = __float2bfloat16(v - __bfloat162float(h));
    }
}

// ---------------------------------------------------------------------------
// Edge scatter: agg[dst] += relu(x_src[src] + ea*We + be)   (vector RED)
// ---------------------------------------------------------------------------
__global__ void edge_scatter_kernel(const float* __restrict__ xsrc,
                                    const int*  __restrict__ src,
                                    const int*  __restrict__ dst,
                                    const float* __restrict__ ea,
                                    const float* __restrict__ We,
                                    const float* __restrict__ be,
                                    float* __restrict__ agg,
                                    int Ecount) {
    int eid = blockIdx.x * 4 + (threadIdx.x >> 6);
    if (eid >= Ecount) return;
    int col = (threadIdx.x & 63) * 4;

    int s = __ldg(src + eid);
    int d = __ldg(dst + eid);
    float a = __ldg(ea + eid);

    float4 x = *(const float4*)(xsrc + (size_t)s * H + col);
    float4 w = __ldg((const float4*)(We + col));
    float4 b = __ldg((const float4*)(be + col));

    float m0 = fmaxf(x.x + fmaf(a, w.x, b.x), 0.f);
    float m1 = fmaxf(x.y + fmaf(a, w.y, b.y), 0.f);
    float m2 = fmaxf(x.z + fmaf(a, w.z, b.z), 0.f);
    float m3 = fmaxf(x.w + fmaf(a, w.w, b.w), 0.f);

    red_v4(agg + (size_t)d * H + col, m0, m1, m2, m3);
}

// ---------------------------------------------------------------------------
// Triple-pass MMA over one 32-K chunk. Passes ordered hh, lh, hl so only one
// live W-fragment array (reloaded in place) -> fits 128-reg budget.
// ---------------------------------------------------------------------------
__device__ __forceinline__ void mma_chunk(
    float c[2][8][4], uint32_t aHi, uint32_t wHi,
    uint32_t a_off, uint32_t w_off, int wm)
{
    const uint32_t ah_base = aHi + (uint32_t)(wm * 2560) + a_off;
    const uint32_t wh_base = wHi + w_off;
#pragma unroll
    for (int ks = 0; ks < 2; ks++) {
        uint32_t ah0[4], ah1[4], al0[4], al1[4];
        uint32_t ab = ah_base + ks * 32;
        ldsm_x4(ah0, ab);
        ldsm_x4(ah1, ab + 1280);
        ldsm_x4(al0, ab + SA_LD);
        ldsm_x4(al1, ab + SA_LD + 1280);
        uint32_t bf[4][4];
        uint32_t wb = wh_base + ks * 32;
#pragma unroll
        for (int n4 = 0; n4 < 4; n4++) ldsm_x4(bf[n4], wb + n4 * 1280);
        // pass 1: Ah * Wh
#pragma unroll
        for (int n4 = 0; n4 < 4; n4++) {
            const int nf = n4 * 2;
            mma_bf16(c[0][nf],     ah0, bf[n4][0], bf[n4][1]);
            mma_bf16(c[0][nf + 1], ah0, bf[n4][2], bf[n4][3]);
            mma_bf16(c[1][nf],     ah1, bf[n4][0], bf[n4][1]);
            mma_bf16(c[1][nf + 1], ah1, bf[n4][2], bf[n4][3]);
        }
        // pass 2: Al * Wh
#pragma unroll
        for (int n4 = 0; n4 < 4; n4++) {
            const int nf = n4 * 2;
            mma_bf16(c[0][nf],     al0, bf[n4][0], bf[n4][1]);
            mma_bf16(c[0][nf + 1], al0, bf[n4][2], bf[n4][3]);
            mma_bf16(c[1][nf],     al1, bf[n4][0], bf[n4][1]);
            mma_bf16(c[1][nf + 1], al1, bf[n4][2], bf[n4][3]);
        }
        // reload W lo in place
#pragma unroll
        for (int n4 = 0; n4 < 4; n4++) ldsm_x4(bf[n4], wb + SW_LD + n4 * 1280);
        // pass 3: Ah * Wl
#pragma unroll
        for (int n4 = 0; n4 < 4; n4++) {
            const int nf = n4 * 2;
            mma_bf16(c[0][nf],     ah0, bf[n4][0], bf[n4][1]);
            mma_bf16(c[0][nf + 1], ah0, bf[n4][2], bf[n4][3]);
            mma_bf16(c[1][nf],     ah1, bf[n4][0], bf[n4][1]);
            mma_bf16(c[1][nf + 1], ah1, bf[n4][2], bf[n4][3]);
        }
    }
}

// ---------------------------------------------------------------------------
// GEMM A: h = relu((X+AGG) @ Wa^T + ba), h stored as bf16 hi/lo planes.
// 64M x 256N tile, 256 thr (8 warps 2m x 4n), 2 CTAs/SM.
// ---------------------------------------------------------------------------
__global__ __launch_bounds__(256, 2) void gemm_a_kernel(
    const float* __restrict__ X, const float* __restrict__ AGG,
    const __nv_bfloat16* __restrict__ WHi, const __nv_bfloat16* __restrict__ WLo,
    const float* __restrict__ ba,
    uint32_t* __restrict__ HHi, uint32_t* __restrict__ HLo, int M)
{
    extern __shared__ char sm[];
    const uint32_t sb = smem_u32(sm);

    const int t = threadIdx.x;
    const int lane = t & 31;
    const int wid = t >> 5;
    const int wm = wid & 1;
    const int wn = wid >> 1;
    const int bm = blockIdx.x * 64;

    float* biasS = (float*)(sm + S_BIAS);
    biasS[t] = ba[t];

    float c[2][8][4];
#pragma unroll
    for (int i = 0; i < 2; i++)
#pragma unroll
        for (int j = 0; j < 8; j++)
#pragma unroll
            for (int e = 0; e < 4; e++) c[i][j][e] = 0.f;

    const int row_a = t >> 2;
    const int kq_a  = t & 3;
    const int grow_a = bm + row_a;
    const bool aval = (grow_a < M);

    auto lda = [&](int ck, float4& v0, float4& v1) {
        if (aval) {
            size_t off = (size_t)grow_a * H + ck * 32 + kq_a * 8;
            const float4* p = (const float4*)(X + off);
            const float4* q = (const float4*)(AGG + off);
            float4 a0 = p[0], a1 = p[1];
            float4 u0 = q[0], u1 = q[1];
            v0.x = a0.x + u0.x; v0.y = a0.y + u0.y;
            v0.z = a0.z + u0.z; v0.w = a0.w + u0.w;
            v1.x = a1.x + u1.x; v1.y = a1.y + u1.y;
            v1.z = a1.z + u1.z; v1.w = a1.w + u1.w;
        } else {
            v0 = make_float4(0.f, 0.f, 0.f, 0.f);
            v1 = v0;
        }
    };
    auto sts_a = [&](int st, float4 v0, float4 v1) {
        float x[8] = {v0.x, v0.y, v0.z, v0.w, v1.x, v1.y, v1.z, v1.w};
        uint32_t hv[4], lv[4];
#pragma unroll
        for (int j = 0; j < 4; j++) {
            __nv_bfloat16 h0 = __float2bfloat16(x[2*j]);
            __nv_bfloat16 h1 = __float2bfloat16(x[2*j+1]);
            float l0 = x[2*j]   - __bfloat162float(h0);
            float l1 = x[2*j+1] - __bfloat162float(h1);
            hv[j] = pack2(__bfloat162float(h0), __bfloat162float(h1));
            lv[j] = pack2(l0, l1);
        }
        uint32_t o = (uint32_t)(row_a * 80 + kq_a * 16);
        *(uint4*)(sm + SA_H(st) + o) = make_uint4(hv[0], hv[1], hv[2], hv[3]);
        *(uint4*)(sm + SA_H(st) + SA_LD + o) = make_uint4(lv[0], lv[1], lv[2], lv[3]);
    };
    auto cpw = [&](int ck, int st) {
        const __nv_bfloat16* sh = WHi + (size_t)t * H + ck * 32;
        const __nv_bfloat16* sl = WLo + (size_t)t * H + ck * 32;
        uint32_t dh = sb + SW_H(st) + t * 80;
#pragma unroll
        for (int q = 0; q < 4; q++) {
            cp16(dh + q * 16, sh + q * 8);
            cp16(dh + SW_LD + q * 16, sl + q * 8);
        }
    };

    const uint32_t a_off = (uint32_t)((lane & 15) * 80 + (lane >> 4) * 16);
    const uint32_t w_off = (uint32_t)((wn * 64 + (lane & 7) + ((lane >> 4) * 8)) * 80
                                      + (((lane >> 3) & 1) * 16));

    float4 p0, p1, n0, n1;
    lda(0, p0, p1);
    cpw(0, 0);
    CP_COMMIT();

#pragma unroll 1
    for (int ck = 0; ck < 8; ck++) {
        const int st = ck & 1;
        sts_a(st, p0, p1);
        if (ck < 7) {
            lda(ck + 1, n0, n1);
            cpw(ck + 1, st ^ 1);
            CP_COMMIT();
            CP_WAIT1();
        } else {
            CP_WAIT0();
        }
        __syncthreads();
        mma_chunk(c, sb + SA_H(st), sb + SW_H(st), a_off, w_off, wm);
        __syncthreads();
        p0 = n0; p1 = n1;
    }

    // epilogue: h = relu(acc + ba) -> global bf16 hi/lo planes
    const int qrow = lane >> 2;
    const int qcol = lane & 3;
#pragma unroll
    for (int mf = 0; mf < 2; mf++)
#pragma unroll
        for (int rh = 0; rh < 2; rh++) {
            int r = wm * 32 + mf * 16 + rh * 8 + qrow;
            int grow = bm + r;
            if (grow >= M) continue;
#pragma unroll
            for (int nf = 0; nf < 8; nf++) {
                int col = wn * 64 + nf * 8 + qcol * 2;
                float z0 = fmaxf(c[mf][nf][rh * 2]     + biasS[col],     0.f);
                float z1 = fmaxf(c[mf][nf][rh * 2 + 1] + biasS[col + 1], 0.f);
                __nv_bfloat16 h0 = __float2bfloat16(z0);
                __nv_bfloat16 h1 = __float2bfloat16(z1);
                float l0 = z0 - __bfloat162float(h0);
                float l1 = z1 - __bfloat162float(h1);
                size_t idx = (size_t)grow * 128 + (col >> 1);
                HHi[idx] = pack2(__bfloat162float(h0), __bfloat162float(h1));
                HLo[idx] = pack2(l0, l1);
            }
        }
}

// ---------------------------------------------------------------------------
// GEMM B: out = LN( h @ Wb^T + bb + X ) * g + beta.  A-operand streamed from
// h bf16 planes via cp.async. Same tiling; LN fused in epilogue.
// ---------------------------------------------------------------------------
__global__ __launch_bounds__(256, 2) void gemm_b_kernel(
    const uint32_t* __restrict__ HHi, const uint32_t* __restrict__ HLo,
    const __nv_bfloat16* __restrict__ WHi, const __nv_bfloat16* __restrict__ WLo,
    const float* __restrict__ bb, const float* __restrict__ X,
    const float* __restrict__ gln, const float* __restrict__ bln,
    float* __restrict__ C, int M)
{
    extern __shared__ char sm[];
    const uint32_t sb = smem_u32(sm);

    const int t = threadIdx.x;
    const int lane = t & 31;
    const int wid = t >> 5;
    const int wm = wid & 1;
    const int wn = wid >> 1;
    const int bm = blockIdx.x * 64;

    float* biasS = (float*)(sm + S_BIAS);
    float* gS    = (float*)(sm + S_G);
    float* bS    = (float*)(sm + S_BETA);
    float* psum  = (float*)(sm + S_PSUM);
    float* psq   = (float*)(sm + S_PSQ);

    biasS[t] = bb[t];
    gS[t] = gln[t];
    bS[t] = bln[t];
    if (t < 64) { psum[t] = 0.f; psq[t] = 0.f; }

    float c[2][8][4];
#pragma unroll
    for (int i = 0; i < 2; i++)
#pragma unroll
        for (int j = 0; j < 8; j++)
#pragma unroll
            for (int e = 0; e < 4; e++) c[i][j][e] = 0.f;

    const int row_a = t >> 2;
    const int kq_a  = t & 3;

    // A chunk via cp.async straight from h planes (bf16, already split)
    auto cpa = [&](int ck, int st) {
        size_t srcb = ((size_t)(bm + row_a) * 512) + ck * 64 + kq_a * 16;
        uint32_t d = sb + SA_H(st) + (uint32_t)(row_a * 80 + kq_a * 16);
        cp16(d, (const char*)HHi + srcb);
        cp16(d + SA_LD, (const char*)HLo + srcb);
    };
    auto cpw = [&](int ck, int st) {
        const __nv_bfloat16* sh = WHi + (size_t)t * H + ck * 32;
        const __nv_bfloat16* sl = WLo + (size_t)t * H + ck * 32;
        uint32_t dh = sb + SW_H(st) + t * 80;
#pragma unroll
        for (int q = 0; q < 4; q++) {
            cp16(dh + q * 16, sh + q * 8);
            cp16(dh + SW_LD + q * 16, sl + q * 8);
        }
    };

    const uint32_t a_off = (uint32_t)((lane & 15) * 80 + (lane >> 4) * 16);
    const uint32_t w_off = (uint32_t)((wn * 64 + (lane & 7) + ((lane >> 4) * 8)) * 80
                                      + (((lane >> 3) & 1) * 16));

    cpa(0, 0);
    cpw(0, 0);
    CP_COMMIT();

#pragma unroll 1
    for (int ck = 0; ck < 8; ck++) {
        const int st = ck & 1;
        if (ck < 7) {
            cpa(ck + 1, st ^ 1);
            cpw(ck + 1, st ^ 1);
            CP_COMMIT();
            CP_WAIT1();
        } else {
            CP_WAIT0();
        }
        __syncthreads();
        mma_chunk(c, sb + SA_H(st), sb + SW_H(st), a_off, w_off, wm);
        __syncthreads();
    }

    // epilogue: LN(acc + bb + X) * g + beta
    const int qrow = lane >> 2;
    const int qcol = lane & 3;
#pragma unroll
    for (int mf = 0; mf < 2; mf++)
#pragma unroll
        for (int rh = 0; rh < 2; rh++) {
            int r = wm * 32 + mf * 16 + rh * 8 + qrow;
            int grow = bm + r;
            float su = 0.f, sq = 0.f;
            if (grow < M) {
                const float* rrow = X + (size_t)grow * H;
#pragma unroll
                for (int nf = 0; nf < 8; nf++) {
                    int col = wn * 64 + nf * 8 + qcol * 2;
                    float2 rv = *(const float2*)(rrow + col);
                    float z0 = c[mf][nf][rh * 2]     + biasS[col]     + rv.x;
                    float z1 = c[mf][nf][rh * 2 + 1] + biasS[col + 1] + rv.y;
                    c[mf][nf][rh * 2]     = z0;
                    c[mf][nf][rh * 2 + 1] = z1;
                    su += z0 + z1;
                    sq += z0 * z0 + z1 * z1;
                }
            }
            su += __shfl_xor_sync(0xFFFFFFFFu, su, 1);
            su += __shfl_xor_sync(0xFFFFFFFFu, su, 2);
            sq += __shfl_xor_sync(0xFFFFFFFFu, sq, 1);
            sq += __shfl_xor_sync(0xFFFFFFFFu, sq, 2);
            if (qcol == 0 && grow < M) {
                atomicAdd(&psum[r], su);
                atomicAdd(&psq[r], sq);
            }
        }
    __syncthreads();
#pragma unroll
    for (int mf = 0; mf < 2; mf++)
#pragma unroll
        for (int rh = 0; rh < 2; rh++) {
            int r = wm * 32 + mf * 16 + rh * 8 + qrow;
            int grow = bm + r;
            if (grow >= M) continue;
            float mu = psum[r] * (1.f / 256.f);
            float var = psq[r] * (1.f / 256.f) - mu * mu;
            float rs = rsqrtf(var + LN_EPS);
            float* crow = C + (size_t)grow * H;
#pragma unroll
            for (int nf = 0; nf < 8; nf++) {
                int col = wn * 64 + nf * 8 + qcol * 2;
                float2 o;
                o.x = (c[mf][nf][rh * 2]     - mu) * rs * gS[col]     + bS[col];
                o.y = (c[mf][nf][rh * 2 + 1] - mu) * rs * gS[col + 1] + bS[col + 1];
                *(float2*)(crow + col) = o;
            }
        }
}

// ---------------------------------------------------------------------------
// launch
// ---------------------------------------------------------------------------
extern "C" void kernel_launch(void* const* d_in, const int* in_sizes, int n_in,
                              void* d_out, int out_size) {
    const float* x_var    = (const float*)d_in[0];
    const float* x_constr = (const float*)d_in[1];
    const int*   ei_v2c   = (const int*)  d_in[2];
    const int*   ei_c2v   = (const int*)  d_in[3];
    const float* ea       = (const float*)d_in[4];
    const float* We1 = (const float*)d_in[5];
    const float* be1 = (const float*)d_in[6];
    const float* W1a = (const float*)d_in[7];
    const float* b1a = (const float*)d_in[8];
    const float* W1b = (const float*)d_in[9];
    const float* b1b = (const float*)d_in[10];
    const float* We2 = (const float*)d_in[11];
    const float* be2 = (const float*)d_in[12];
    const float* W2a = (const float*)d_in[13];
    const float* b2a = (const float*)d_in[14];
    const float* W2b = (const float*)d_in[15];
    const float* b2b = (const float*)d_in[16];
    const float* g_constr    = (const float*)d_in[17];
    const float* beta_constr = (const float*)d_in[18];
    const float* g_var       = (const float*)d_in[19];
    const float* beta_var    = (const float*)d_in[20];

    const int NVr = in_sizes[0] / H;
    const int NCr = in_sizes[1] / H;
    const int Ecnt = in_sizes[4];

    float* agg;
    cudaGetSymbolAddress((void**)&agg, g_agg);
    uint32_t *hhi, *hlo;
    cudaGetSymbolAddress((void**)&hhi, g_hhi);
    cudaGetSymbolAddress((void**)&hlo, g_hlo);
    __nv_bfloat16* wt;
    cudaGetSymbolAddress((void**)&wt, g_wt);
    __nv_bfloat16* wt1a_h = wt;             __nv_bfloat16* wt1a_l = wt + H*H;
    __nv_bfloat16* wt1b_h = wt + 2*H*H;     __nv_bfloat16* wt1b_l = wt + 3*H*H;
    __nv_bfloat16* wt2a_h = wt + 4*H*H;     __nv_bfloat16* wt2a_l = wt + 5*H*H;
    __nv_bfloat16* wt2b_h = wt + 6*H*H;     __nv_bfloat16* wt2b_l = wt + 7*H*H;

    cudaFuncSetAttribute(gemm_a_kernel,
                         cudaFuncAttributeMaxDynamicSharedMemorySize, SMEM_SZ);
    cudaFuncSetAttribute(gemm_b_kernel,
                         cudaFuncAttributeMaxDynamicSharedMemorySize, SMEM_SZ);

    float* out_var    = (float*)d_out;
    float* out_constr = (float*)d_out + (size_t)NVr * H;

    const int edge_blocks = (Ecnt + 3) / 4;

    wprep4_kernel<<<256, 256>>>(W1a, W1b, W2a, W2b, wt);

    // ---- stage 1: var -> constr ----
    {
        int n4 = NCr * H / 4;
        zero_kernel<<<(n4 + 255) / 256, 256>>>((float4*)agg, n4);
        edge_scatter_kernel<<<edge_blocks, 256>>>(x_var, ei_v2c, ei_v2c + Ecnt,
                                                  ea, We1, be1, agg, Ecnt);
        int gx = (NCr + 63) / 64;
        gemm_a_kernel<<<gx, 256, SMEM_SZ>>>(
            x_constr, agg, wt1a_h, wt1a_l, b1a, hhi, hlo, NCr);
        gemm_b_kernel<<<gx, 256, SMEM_SZ>>>(
            hhi, hlo, wt1b_h, wt1b_l, b1b, x_constr,
            g_constr, beta_constr, out_constr, NCr);
    }

    // ---- stage 2: constr -> var (reads LN'd x_constr from d_out) ----
    {
        int n4 = NVr * H / 4;
        zero_kernel<<<(n4 + 255) / 256, 256>>>((float4*)agg, n4);
        edge_scatter_kernel<<<edge_blocks, 256>>>(out_constr, ei_c2v, ei_c2v + Ecnt,
                                                  ea, We2, be2, agg, Ecnt);
        int gx = (NVr + 63) / 64;
        gemm_a_kernel<<<gx, 256, SMEM_SZ>>>(
            x_var, agg, wt2a_h, wt2a_l, b2a, hhi, hlo, NVr);
        gemm_b_kernel<<<gx, 256, SMEM_SZ>>>(
            hhi, hlo, wt2b_h, wt2b_l, b2b, x_var,
            g_var, beta_var, out_var, NVr);
    }
}